// round 1
// baseline (speedup 1.0000x reference)
#include <cuda_runtime.h>
#include <cstddef>

// Problem constants
#define Bb 4
#define Nn 4096
#define DIMV 512
#define Hh 8
#define Dd 64
#define Mm 256
#define BHc 32
#define QSCALE 0.125f

// ---------------- scratch (device globals; no allocation allowed) ----------------
__device__ float g_xn  [Bb*Nn*DIMV];          // 8.39M
__device__ float g_qkv [Bb*Nn*3*DIMV];        // 25.2M
__device__ float g_q   [BHc*Nn*Dd];
__device__ float g_k   [BHc*Nn*Dd];
__device__ float g_v   [BHc*Nn*Dd];
__device__ float g_ql  [BHc*Mm*Dd];
__device__ float g_kl  [BHc*Mm*Dd];
__device__ float g_s1  [BHc*Nn*Mm];           // attn1  33.5M
__device__ float g_s3  [BHc*Mm*Nn];           // attn3  33.5M
__device__ float g_a2  [BHc*Mm*Mm];
__device__ float g_z   [BHc*Mm*Mm];
__device__ float g_zn  [BHc*Mm*Mm];
__device__ float g_az  [BHc*Mm*Mm];
__device__ float g_w1  [BHc*Mm*Mm];
__device__ float g_w2  [BHc*Mm*Mm];
__device__ float g_a3v [BHc*Mm*Dd];
__device__ float g_t1  [BHc*Nn*Mm];           // 33.5M
__device__ float g_outh[BHc*Nn*Dd];
__device__ float g_outm[Bb*Nn*DIMV];
__device__ float g_ms1, g_ms2;                // global max row-sum / col-sum of attn2

// ---------------- small kernels ----------------
__global__ void k_init() { g_ms1 = 0.f; g_ms2 = 0.f; }

__global__ void k_ln(const float* __restrict__ x, const float* __restrict__ gamma,
                     const float* __restrict__ beta) {
    int r = blockIdx.x, t = threadIdx.x;
    const float* xp = x + (size_t)r * DIMV;
    float v0 = xp[t], v1 = xp[t + 256];
    __shared__ float red[256];
    red[t] = v0 + v1; __syncthreads();
    for (int s = 128; s; s >>= 1) { if (t < s) red[t] += red[t + s]; __syncthreads(); }
    float mean = red[0] * (1.f / 512.f);
    __syncthreads();
    float d0 = v0 - mean, d1 = v1 - mean;
    red[t] = d0 * d0 + d1 * d1; __syncthreads();
    for (int s = 128; s; s >>= 1) { if (t < s) red[t] += red[t + s]; __syncthreads(); }
    float rstd = rsqrtf(red[0] * (1.f / 512.f) + 1e-5f);
    float* o = g_xn + (size_t)r * DIMV;
    o[t]       = d0 * rstd * gamma[t]       + beta[t];
    o[t + 256] = d1 * rstd * gamma[t + 256] + beta[t + 256];
}

__global__ void k_split() {
    int idx = blockIdx.x * 256 + threadIdx.x;          // < 16384*1536
    int r = idx / 1536, c = idx % 1536;
    int which = c >> 9, inner = c & 511;
    int h = inner >> 6, d = inner & 63;
    int b = r >> 12, n = r & 4095;
    float v = g_qkv[idx];
    size_t dst = (((size_t)(b * 8 + h)) * 4096 + n) * 64 + d;
    if (which == 0)      g_q[dst] = v * QSCALE;
    else if (which == 1) g_k[dst] = v;
    else                 g_v[dst] = v;
}

__global__ void k_land() {
    int idx = blockIdx.x * 256 + threadIdx.x;          // < 2*32*256*64
    int sel = idx >= (BHc * Mm * Dd);
    int e = idx & (BHc * Mm * Dd - 1);
    int bh = e >> 14, j = (e >> 6) & 255, d = e & 63;
    const float* src = sel ? g_k : g_q;
    const float* p = src + ((size_t)bh * 4096 + j * 16) * 64 + d;
    float s = 0.f;
#pragma unroll
    for (int t = 0; t < 16; t++) s += p[t * 64];
    (sel ? g_kl : g_ql)[(size_t)bh * 16384 + j * 64 + d] = s * (1.f / 16.f);
}

template <int E>
__global__ void k_softmax(float* __restrict__ p) {   // row length = 256*E
    int row = blockIdx.x, t = threadIdx.x;
    p += (size_t)row * (256 * E);
    float rv[E];
    float m = -1e30f;
#pragma unroll
    for (int i = 0; i < E; i++) { rv[i] = p[t + (i << 8)]; m = fmaxf(m, rv[i]); }
    __shared__ float red[256];
    red[t] = m; __syncthreads();
    for (int s = 128; s; s >>= 1) { if (t < s) red[t] = fmaxf(red[t], red[t + s]); __syncthreads(); }
    m = red[0]; __syncthreads();
    float sum = 0.f;
#pragma unroll
    for (int i = 0; i < E; i++) { rv[i] = __expf(rv[i] - m); sum += rv[i]; }
    red[t] = sum; __syncthreads();
    for (int s = 128; s; s >>= 1) { if (t < s) red[t] += red[t + s]; __syncthreads(); }
    float inv = 1.f / red[0];
#pragma unroll
    for (int i = 0; i < E; i++) p[t + (i << 8)] = rv[i] * inv;
}

__global__ void k_sums(const float* __restrict__ a) {
    int mat = blockIdx.x, t = threadIdx.x;
    const float* A = a + (size_t)mat * 65536;
    float cs = 0.f, rs = 0.f;
    for (int i = 0; i < 256; i++) { cs += A[i * 256 + t]; rs += A[t * 256 + i]; }
    __shared__ float red[256];
    red[t] = rs; __syncthreads();
    for (int s = 128; s; s >>= 1) { if (t < s) red[t] = fmaxf(red[t], red[t + s]); __syncthreads(); }
    if (!t) atomicMax((int*)&g_ms1, __float_as_int(red[0]));
    __syncthreads();
    red[t] = cs; __syncthreads();
    for (int s = 128; s; s >>= 1) { if (t < s) red[t] = fmaxf(red[t], red[t + s]); __syncthreads(); }
    if (!t) atomicMax((int*)&g_ms2, __float_as_int(red[0]));
}

__global__ void k_z0(const float* __restrict__ a) {
    int idx = blockIdx.x * 256 + threadIdx.x;          // < 32*65536
    float inv = 1.f / (g_ms1 * g_ms2);
    int mat = idx >> 16, r = (idx >> 8) & 255, c = idx & 255;
    g_z[idx] = a[((size_t)mat << 16) + (c << 8) + r] * inv;
}

__global__ void k_conv(const float* __restrict__ w) {
    int idx = blockIdx.x * 256 + threadIdx.x;          // < 32*4096*64
    int d = idx & 63, n = (idx >> 6) & 4095, bh = idx >> 18;
    int h = bh & 7;
    const float* vp = g_v + ((size_t)bh << 18);
    float acc = 0.f;
#pragma unroll
    for (int t = 0; t < 33; t++) {
        int nn = n + t - 16;
        if (nn >= 0 && nn < 4096) acc += w[h * 33 + t] * vp[nn * 64 + d];
    }
    g_outh[idx] += acc;
}

__global__ void k_merge() {
    int idx = blockIdx.x * 256 + threadIdx.x;          // < 16384*512
    int c = idx & 511, r = idx >> 9;
    int h = c >> 6, d = c & 63, b = r >> 12, n = r & 4095;
    g_outm[idx] = g_outh[(((size_t)(b * 8 + h)) * 4096 + n) * 64 + d];
}

// ---------------- generic batched SGEMM: 64x64x16 tile, 256 thr, 4x4 micro ----------------
// C = cM*(A@B[^T]) + cA*AE[r,c]  (+ bias[c]) (+ resid[r,c])
__global__ void sgemm(const float* __restrict__ A, const float* __restrict__ Bm,
                      float* __restrict__ C, int Kr,
                      int lda, int ldb, int ldc,
                      long sA, long sB, long sC,
                      int transB, float cM, float cA, const float* __restrict__ AE,
                      const float* __restrict__ bias, const float* __restrict__ resid) {
    int bz = blockIdx.z;
    A  += (size_t)bz * sA;
    Bm += (size_t)bz * sB;
    C  += (size_t)bz * sC;

    __shared__ float As[16][65];
    __shared__ float Bs[16][68];

    int tid = threadIdx.x;
    int tx = tid & 15, ty = tid >> 4;
    int rowBase = blockIdx.y * 64, colBase = blockIdx.x * 64;
    int am = tid >> 2, ak = (tid & 3) * 4;

    float acc[4][4];
#pragma unroll
    for (int i = 0; i < 4; i++)
#pragma unroll
        for (int j = 0; j < 4; j++) acc[i][j] = 0.f;

    for (int k0 = 0; k0 < Kr; k0 += 16) {
        float4 a4 = *(const float4*)(A + (size_t)(rowBase + am) * lda + k0 + ak);
        As[ak + 0][am] = a4.x; As[ak + 1][am] = a4.y;
        As[ak + 2][am] = a4.z; As[ak + 3][am] = a4.w;
        if (transB) {
            float4 b4 = *(const float4*)(Bm + (size_t)(colBase + am) * ldb + k0 + ak);
            Bs[ak + 0][am] = b4.x; Bs[ak + 1][am] = b4.y;
            Bs[ak + 2][am] = b4.z; Bs[ak + 3][am] = b4.w;
        } else {
            int bk = tid >> 4, bn = (tid & 15) * 4;
            float4 b4 = *(const float4*)(Bm + (size_t)(k0 + bk) * ldb + colBase + bn);
            *(float4*)&Bs[bk][bn] = b4;
        }
        __syncthreads();
#pragma unroll
        for (int kk = 0; kk < 16; kk++) {
            float ra[4];
#pragma unroll
            for (int i = 0; i < 4; i++) ra[i] = As[kk][ty * 4 + i];
            float4 b4 = *(const float4*)&Bs[kk][tx * 4];
            float rb[4] = {b4.x, b4.y, b4.z, b4.w};
#pragma unroll
            for (int i = 0; i < 4; i++)
#pragma unroll
                for (int j = 0; j < 4; j++) acc[i][j] += ra[i] * rb[j];
        }
        __syncthreads();
    }

#pragma unroll
    for (int i = 0; i < 4; i++) {
        int r = rowBase + ty * 4 + i;
#pragma unroll
        for (int j = 0; j < 4; j++) {
            int c = colBase + tx * 4 + j;
            float v = cM * acc[i][j];
            if (AE)    v += cA * AE[(size_t)bz * sA + (size_t)r * lda + c];
            if (bias)  v += bias[c];
            if (resid) v += resid[(size_t)r * ldc + c];
            C[(size_t)r * ldc + c] = v;
        }
    }
}

// ---------------- host orchestration ----------------
extern "C" void kernel_launch(void* const* d_in, const int* in_sizes, int n_in,
                              void* d_out, int out_size) {
    const float* x      = (const float*)d_in[0];
    const float* gamma  = (const float*)d_in[1];
    const float* beta   = (const float*)d_in[2];
    const float* w_qkv  = (const float*)d_in[3];
    const float* w_out  = (const float*)d_in[4];
    const float* b_out  = (const float*)d_in[5];
    const float* conv_w = (const float*)d_in[6];
    float* out = (float*)d_out;

    void* tp;
    cudaGetSymbolAddress(&tp, g_xn);   float* p_xn  = (float*)tp;
    cudaGetSymbolAddress(&tp, g_qkv);  float* p_qkv = (float*)tp;
    cudaGetSymbolAddress(&tp, g_q);    float* p_q   = (float*)tp;
    cudaGetSymbolAddress(&tp, g_k);    float* p_k   = (float*)tp;
    cudaGetSymbolAddress(&tp, g_v);    float* p_v   = (float*)tp;
    cudaGetSymbolAddress(&tp, g_ql);   float* p_ql  = (float*)tp;
    cudaGetSymbolAddress(&tp, g_kl);   float* p_kl  = (float*)tp;
    cudaGetSymbolAddress(&tp, g_s1);   float* p_s1  = (float*)tp;
    cudaGetSymbolAddress(&tp, g_s3);   float* p_s3  = (float*)tp;
    cudaGetSymbolAddress(&tp, g_a2);   float* p_a2  = (float*)tp;
    cudaGetSymbolAddress(&tp, g_z);    float* p_z   = (float*)tp;
    cudaGetSymbolAddress(&tp, g_zn);   float* p_zn  = (float*)tp;
    cudaGetSymbolAddress(&tp, g_az);   float* p_az  = (float*)tp;
    cudaGetSymbolAddress(&tp, g_w1);   float* p_w1  = (float*)tp;
    cudaGetSymbolAddress(&tp, g_w2);   float* p_w2  = (float*)tp;
    cudaGetSymbolAddress(&tp, g_a3v);  float* p_a3v = (float*)tp;
    cudaGetSymbolAddress(&tp, g_t1);   float* p_t1  = (float*)tp;
    cudaGetSymbolAddress(&tp, g_outh); float* p_oh  = (float*)tp;
    cudaGetSymbolAddress(&tp, g_outm); float* p_om  = (float*)tp;

    k_init<<<1, 1>>>();
    k_ln<<<Bb * Nn, 256>>>(x, gamma, beta);

    // qkv = xn @ w_qkv   [16384,512]@[512,1536]
    sgemm<<<dim3(1536 / 64, 16384 / 64, 1), 256>>>(
        p_xn, w_qkv, p_qkv, 512, 512, 1536, 1536, 0, 0, 0, 0, 1.f, 0.f,
        nullptr, nullptr, nullptr);
    k_split<<<(Bb * Nn * 3 * DIMV) / 256, 256>>>();
    k_land<<<(2 * BHc * Mm * Dd) / 256, 256>>>();

    // S1 = q @ kl^T   per-bh [4096,64]@[64,256]^T
    sgemm<<<dim3(4, 64, 32), 256>>>(p_q, p_kl, p_s1, 64, 64, 64, 256,
        (long)Nn * Dd, (long)Mm * Dd, (long)Nn * Mm, 1, 1.f, 0.f, nullptr, nullptr, nullptr);
    k_softmax<1><<<BHc * Nn, 256>>>(p_s1);

    // A2 = ql @ kl^T   [256,64]@[64,256]^T
    sgemm<<<dim3(4, 4, 32), 256>>>(p_ql, p_kl, p_a2, 64, 64, 64, 256,
        (long)Mm * Dd, (long)Mm * Dd, (long)Mm * Mm, 1, 1.f, 0.f, nullptr, nullptr, nullptr);
    k_softmax<1><<<BHc * Mm, 256>>>(p_a2);

    // S3 = ql @ k^T   [256,64]@[64,4096]^T
    sgemm<<<dim3(64, 4, 32), 256>>>(p_ql, p_k, p_s3, 64, 64, 64, 4096,
        (long)Mm * Dd, (long)Nn * Dd, (long)Mm * Nn, 1, 1.f, 0.f, nullptr, nullptr, nullptr);
    k_softmax<16><<<BHc * Mm, 256>>>(p_s3);

    // pinv init: Z = A2^T / (max_rowsum * max_colsum)  (global maxima)
    k_sums<<<BHc, 256>>>(p_a2);
    k_z0<<<(BHc * Mm * Mm) / 256, 256>>>(p_a2);

    // Newton-Schulz: 6 iters, each 4 batched 256^3 GEMMs
    float* zc = p_z; float* zo = p_zn;
    long sq = (long)Mm * Mm;
    for (int it = 0; it < 6; it++) {
        sgemm<<<dim3(4, 4, 32), 256>>>(p_a2, zc, p_az, 256, 256, 256, 256,
            sq, sq, sq, 0, 1.f, 0.f, nullptr, nullptr, nullptr);
        sgemm<<<dim3(4, 4, 32), 256>>>(p_az, p_az, p_w1, 256, 256, 256, 256,
            sq, sq, sq, 0, -1.f, 7.f, p_az, nullptr, nullptr);
        sgemm<<<dim3(4, 4, 32), 256>>>(p_az, p_w1, p_w2, 256, 256, 256, 256,
            sq, sq, sq, 0, -1.f, 15.f, p_az, nullptr, nullptr);
        sgemm<<<dim3(4, 4, 32), 256>>>(zc, p_w2, zo, 256, 256, 256, 256,
            sq, sq, sq, 0, -0.25f, 3.25f, zc, nullptr, nullptr);
        float* t = zc; zc = zo; zo = t;
    }

    // A3V = S3 @ v   [256,4096]@[4096,64]
    sgemm<<<dim3(1, 4, 32), 256>>>(p_s3, p_v, p_a3v, 4096, 4096, 64, 64,
        (long)Mm * Nn, (long)Nn * Dd, (long)Mm * Dd, 0, 1.f, 0.f, nullptr, nullptr, nullptr);

    // T1 = S1 @ Z   [4096,256]@[256,256]
    sgemm<<<dim3(4, 64, 32), 256>>>(p_s1, zc, p_t1, 256, 256, 256, 256,
        (long)Nn * Mm, sq, (long)Nn * Mm, 0, 1.f, 0.f, nullptr, nullptr, nullptr);

    // OUTH = T1 @ A3V   [4096,256]@[256,64]
    sgemm<<<dim3(1, 64, 32), 256>>>(p_t1, p_a3v, p_oh, 256, 256, 64, 64,
        (long)Nn * Mm, (long)Mm * Dd, (long)Nn * Dd, 0, 1.f, 0.f, nullptr, nullptr, nullptr);

    // residual depthwise conv of v added to OUTH
    k_conv<<<(BHc * Nn * Dd) / 256, 256>>>(conv_w);
    k_merge<<<(Bb * Nn * DIMV) / 256, 256>>>();

    // final: out = OUTM @ w_out + b_out + x
    sgemm<<<dim3(512 / 64, 16384 / 64, 1), 256>>>(p_om, w_out, out, 512, 512, 512, 512,
        0, 0, 0, 0, 1.f, 0.f, nullptr, b_out, x);
}

// round 2
// speedup vs baseline: 1.5097x; 1.5097x over previous
#include <cuda_runtime.h>
#include <cstddef>

// Problem constants
#define Bb 4
#define Nn 4096
#define DIMV 512
#define Hh 8
#define Dd 64
#define Mm 256
#define BHc 32
#define QSCALE 0.125f

// ---------------- scratch (device globals; no allocation allowed) ----------------
__device__ float g_xn  [Bb*Nn*DIMV];
__device__ float g_qkv [Bb*Nn*3*DIMV];
__device__ float g_q   [BHc*Nn*Dd];
__device__ float g_k   [BHc*Nn*Dd];
__device__ float g_v   [BHc*Nn*Dd];
__device__ float g_ql  [BHc*Mm*Dd];
__device__ float g_kl  [BHc*Mm*Dd];
__device__ float g_s1  [BHc*Nn*Mm];
__device__ float g_s3  [BHc*Mm*Nn];
__device__ float g_a2  [BHc*Mm*Mm];
__device__ float g_z   [BHc*Mm*Mm];
__device__ float g_zn  [BHc*Mm*Mm];
__device__ float g_az  [BHc*Mm*Mm];
__device__ float g_w1  [BHc*Mm*Mm];
__device__ float g_w2  [BHc*Mm*Mm];
__device__ float g_a3v [BHc*Mm*Dd];
__device__ float g_t1  [BHc*Nn*Mm];
__device__ float g_outh[BHc*Nn*Dd];
__device__ float g_outm[Bb*Nn*DIMV];
__device__ float g_ms1, g_ms2;

// ---------------- small kernels ----------------
__global__ void k_init() { g_ms1 = 0.f; g_ms2 = 0.f; }

__global__ void k_ln(const float* __restrict__ x, const float* __restrict__ gamma,
                     const float* __restrict__ beta) {
    int r = blockIdx.x, t = threadIdx.x;
    const float* xp = x + (size_t)r * DIMV;
    float v0 = xp[t], v1 = xp[t + 256];
    __shared__ float red[256];
    red[t] = v0 + v1; __syncthreads();
    for (int s = 128; s; s >>= 1) { if (t < s) red[t] += red[t + s]; __syncthreads(); }
    float mean = red[0] * (1.f / 512.f);
    __syncthreads();
    float d0 = v0 - mean, d1 = v1 - mean;
    red[t] = d0 * d0 + d1 * d1; __syncthreads();
    for (int s = 128; s; s >>= 1) { if (t < s) red[t] += red[t + s]; __syncthreads(); }
    float rstd = rsqrtf(red[0] * (1.f / 512.f) + 1e-5f);
    float* o = g_xn + (size_t)r * DIMV;
    o[t]       = d0 * rstd * gamma[t]       + beta[t];
    o[t + 256] = d1 * rstd * gamma[t + 256] + beta[t + 256];
}

__global__ void k_split() {
    int idx = blockIdx.x * 256 + threadIdx.x;
    int r = idx / 1536, c = idx % 1536;
    int which = c >> 9, inner = c & 511;
    int h = inner >> 6, d = inner & 63;
    int b = r >> 12, n = r & 4095;
    float v = g_qkv[idx];
    size_t dst = (((size_t)(b * 8 + h)) * 4096 + n) * 64 + d;
    if (which == 0)      g_q[dst] = v * QSCALE;
    else if (which == 1) g_k[dst] = v;
    else                 g_v[dst] = v;
}

__global__ void k_land() {
    int idx = blockIdx.x * 256 + threadIdx.x;
    int sel = idx >= (BHc * Mm * Dd);
    int e = idx & (BHc * Mm * Dd - 1);
    int bh = e >> 14, j = (e >> 6) & 255, d = e & 63;
    const float* src = sel ? g_k : g_q;
    const float* p = src + ((size_t)bh * 4096 + j * 16) * 64 + d;
    float s = 0.f;
#pragma unroll
    for (int t = 0; t < 16; t++) s += p[t * 64];
    (sel ? g_kl : g_ql)[(size_t)bh * 16384 + j * 64 + d] = s * (1.f / 16.f);
}

template <int E>
__global__ void k_softmax(float* __restrict__ p) {
    int row = blockIdx.x, t = threadIdx.x;
    p += (size_t)row * (256 * E);
    float rv[E];
    float m = -1e30f;
#pragma unroll
    for (int i = 0; i < E; i++) { rv[i] = p[t + (i << 8)]; m = fmaxf(m, rv[i]); }
    __shared__ float red[256];
    red[t] = m; __syncthreads();
    for (int s = 128; s; s >>= 1) { if (t < s) red[t] = fmaxf(red[t], red[t + s]); __syncthreads(); }
    m = red[0]; __syncthreads();
    float sum = 0.f;
#pragma unroll
    for (int i = 0; i < E; i++) { rv[i] = __expf(rv[i] - m); sum += rv[i]; }
    red[t] = sum; __syncthreads();
    for (int s = 128; s; s >>= 1) { if (t < s) red[t] += red[t + s]; __syncthreads(); }
    float inv = 1.f / red[0];
#pragma unroll
    for (int i = 0; i < E; i++) p[t + (i << 8)] = rv[i] * inv;
}

__global__ void k_sums(const float* __restrict__ a) {
    int mat = blockIdx.x, t = threadIdx.x;
    const float* A = a + (size_t)mat * 65536;
    float cs = 0.f, rs = 0.f;
    for (int i = 0; i < 256; i++) { cs += A[i * 256 + t]; rs += A[t * 256 + i]; }
    __shared__ float red[256];
    red[t] = rs; __syncthreads();
    for (int s = 128; s; s >>= 1) { if (t < s) red[t] = fmaxf(red[t], red[t + s]); __syncthreads(); }
    if (!t) atomicMax((int*)&g_ms1, __float_as_int(red[0]));
    __syncthreads();
    red[t] = cs; __syncthreads();
    for (int s = 128; s; s >>= 1) { if (t < s) red[t] = fmaxf(red[t], red[t + s]); __syncthreads(); }
    if (!t) atomicMax((int*)&g_ms2, __float_as_int(red[0]));
}

__global__ void k_z0(const float* __restrict__ a) {
    int idx = blockIdx.x * 256 + threadIdx.x;
    float inv = 1.f / (g_ms1 * g_ms2);
    int mat = idx >> 16, r = (idx >> 8) & 255, c = idx & 255;
    g_z[idx] = a[((size_t)mat << 16) + (c << 8) + r] * inv;
}

__global__ void k_conv(const float* __restrict__ w) {
    int idx = blockIdx.x * 256 + threadIdx.x;
    int d = idx & 63, n = (idx >> 6) & 4095, bh = idx >> 18;
    int h = bh & 7;
    const float* vp = g_v + ((size_t)bh << 18);
    float acc = 0.f;
#pragma unroll
    for (int t = 0; t < 33; t++) {
        int nn = n + t - 16;
        if (nn >= 0 && nn < 4096) acc += w[h * 33 + t] * vp[nn * 64 + d];
    }
    g_outh[idx] += acc;
}

__global__ void k_merge() {
    int idx = blockIdx.x * 256 + threadIdx.x;
    int c = idx & 511, r = idx >> 9;
    int h = c >> 6, d = c & 63, b = r >> 12, n = r & 4095;
    g_outm[idx] = g_outh[(((size_t)(b * 8 + h)) * 4096 + n) * 64 + d];
}

// ---------------- TF32 tensor-core batched GEMM ----------------
// Tile 128x64x16, 256 threads (8 warps, 4x2), warp tile 32x32 via mma.m16n8k8.
// C = cM*(A@B[^T]) + cA*AE + bias[c] + resid[r,c]
__device__ __forceinline__ unsigned f2tf(float f) {
    unsigned u;
    asm("cvt.rna.tf32.f32 %0, %1;" : "=r"(u) : "f"(f));
    return u;
}

__global__ __launch_bounds__(256) void tgemm(
    const float* __restrict__ A, const float* __restrict__ Bm,
    float* __restrict__ C, int Kr,
    int lda, int ldb, int ldc,
    long sA, long sB, long sC,
    int transB, float cM, float cA, const float* __restrict__ AE,
    const float* __restrict__ bias, const float* __restrict__ resid) {
    int bz = blockIdx.z;
    A  += (size_t)bz * sA;
    Bm += (size_t)bz * sB;
    C  += (size_t)bz * sC;

    __shared__ unsigned As[128][20];
    __shared__ unsigned Bs[64][20];

    int tid = threadIdx.x, lane = tid & 31, w = tid >> 5;
    int wr = w >> 1, wc = w & 1;
    int rowBase = blockIdx.y * 128, colBase = blockIdx.x * 64;

    float acc[2][4][4];
#pragma unroll
    for (int mi = 0; mi < 2; mi++)
#pragma unroll
        for (int ni = 0; ni < 4; ni++)
#pragma unroll
            for (int q = 0; q < 4; q++) acc[mi][ni][q] = 0.f;

    for (int k0 = 0; k0 < Kr; k0 += 16) {
        // A tile: 128x16 = 512 float4, 2 per thread
#pragma unroll
        for (int i = 0; i < 2; i++) {
            int idx = tid + i * 256;
            int r = idx >> 2, cg = (idx & 3) * 4;
            float4 a4 = *(const float4*)(A + (size_t)(rowBase + r) * lda + k0 + cg);
            uint4 u;
            u.x = f2tf(a4.x); u.y = f2tf(a4.y); u.z = f2tf(a4.z); u.w = f2tf(a4.w);
            *(uint4*)&As[r][cg] = u;
        }
        // B tile -> Bs[n][k]
        if (transB) {
            int r = tid >> 2, cg = (tid & 3) * 4;   // r: n-index, cg: k
            float4 b4 = *(const float4*)(Bm + (size_t)(colBase + r) * ldb + k0 + cg);
            uint4 u;
            u.x = f2tf(b4.x); u.y = f2tf(b4.y); u.z = f2tf(b4.z); u.w = f2tf(b4.w);
            *(uint4*)&Bs[r][cg] = u;
        } else {
            int kk = tid >> 4, n0 = (tid & 15) * 4;  // k row, 4 n's
            float4 b4 = *(const float4*)(Bm + (size_t)(k0 + kk) * ldb + colBase + n0);
            Bs[n0 + 0][kk] = f2tf(b4.x);
            Bs[n0 + 1][kk] = f2tf(b4.y);
            Bs[n0 + 2][kk] = f2tf(b4.z);
            Bs[n0 + 3][kk] = f2tf(b4.w);
        }
        __syncthreads();

#pragma unroll
        for (int ks = 0; ks < 2; ks++) {
            int kb = ks * 8;
            unsigned ar[2][4], br[4][2];
#pragma unroll
            for (int mi = 0; mi < 2; mi++) {
                int r = wr * 32 + mi * 16 + (lane >> 2);
                ar[mi][0] = As[r][kb + (lane & 3)];
                ar[mi][1] = As[r + 8][kb + (lane & 3)];
                ar[mi][2] = As[r][kb + (lane & 3) + 4];
                ar[mi][3] = As[r + 8][kb + (lane & 3) + 4];
            }
#pragma unroll
            for (int ni = 0; ni < 4; ni++) {
                int n = wc * 32 + ni * 8 + (lane >> 2);
                br[ni][0] = Bs[n][kb + (lane & 3)];
                br[ni][1] = Bs[n][kb + (lane & 3) + 4];
            }
#pragma unroll
            for (int mi = 0; mi < 2; mi++)
#pragma unroll
                for (int ni = 0; ni < 4; ni++) {
                    asm volatile(
                        "mma.sync.aligned.m16n8k8.row.col.f32.tf32.tf32.f32 "
                        "{%0,%1,%2,%3}, {%4,%5,%6,%7}, {%8,%9}, {%0,%1,%2,%3};"
                        : "+f"(acc[mi][ni][0]), "+f"(acc[mi][ni][1]),
                          "+f"(acc[mi][ni][2]), "+f"(acc[mi][ni][3])
                        : "r"(ar[mi][0]), "r"(ar[mi][1]), "r"(ar[mi][2]), "r"(ar[mi][3]),
                          "r"(br[ni][0]), "r"(br[ni][1]));
                }
        }
        __syncthreads();
    }

    // epilogue
#pragma unroll
    for (int mi = 0; mi < 2; mi++) {
#pragma unroll
        for (int ni = 0; ni < 4; ni++) {
            int r0 = rowBase + wr * 32 + mi * 16 + (lane >> 2);
            int c0 = colBase + wc * 32 + ni * 8 + (lane & 3) * 2;
#pragma unroll
            for (int q = 0; q < 4; q++) {
                int r = r0 + (q >> 1) * 8;
                int c = c0 + (q & 1);
                float v = cM * acc[mi][ni][q];
                if (AE)    v += cA * AE[(size_t)bz * sA + (size_t)r * lda + c];
                if (bias)  v += bias[c];
                if (resid) v += resid[(size_t)r * ldc + c];
                C[(size_t)r * ldc + c] = v;
            }
        }
    }
}

// ---------------- host orchestration ----------------
extern "C" void kernel_launch(void* const* d_in, const int* in_sizes, int n_in,
                              void* d_out, int out_size) {
    const float* x      = (const float*)d_in[0];
    const float* gamma  = (const float*)d_in[1];
    const float* beta   = (const float*)d_in[2];
    const float* w_qkv  = (const float*)d_in[3];
    const float* w_out  = (const float*)d_in[4];
    const float* b_out  = (const float*)d_in[5];
    const float* conv_w = (const float*)d_in[6];
    float* out = (float*)d_out;

    void* tp;
    cudaGetSymbolAddress(&tp, g_xn);   float* p_xn  = (float*)tp;
    cudaGetSymbolAddress(&tp, g_qkv);  float* p_qkv = (float*)tp;
    cudaGetSymbolAddress(&tp, g_q);    float* p_q   = (float*)tp;
    cudaGetSymbolAddress(&tp, g_k);    float* p_k   = (float*)tp;
    cudaGetSymbolAddress(&tp, g_v);    float* p_v   = (float*)tp;
    cudaGetSymbolAddress(&tp, g_ql);   float* p_ql  = (float*)tp;
    cudaGetSymbolAddress(&tp, g_kl);   float* p_kl  = (float*)tp;
    cudaGetSymbolAddress(&tp, g_s1);   float* p_s1  = (float*)tp;
    cudaGetSymbolAddress(&tp, g_s3);   float* p_s3  = (float*)tp;
    cudaGetSymbolAddress(&tp, g_a2);   float* p_a2  = (float*)tp;
    cudaGetSymbolAddress(&tp, g_z);    float* p_z   = (float*)tp;
    cudaGetSymbolAddress(&tp, g_zn);   float* p_zn  = (float*)tp;
    cudaGetSymbolAddress(&tp, g_az);   float* p_az  = (float*)tp;
    cudaGetSymbolAddress(&tp, g_w1);   float* p_w1  = (float*)tp;
    cudaGetSymbolAddress(&tp, g_w2);   float* p_w2  = (float*)tp;
    cudaGetSymbolAddress(&tp, g_a3v);  float* p_a3v = (float*)tp;
    cudaGetSymbolAddress(&tp, g_t1);   float* p_t1  = (float*)tp;
    cudaGetSymbolAddress(&tp, g_outh); float* p_oh  = (float*)tp;
    cudaGetSymbolAddress(&tp, g_outm); float* p_om  = (float*)tp;

    k_init<<<1, 1>>>();
    k_ln<<<Bb * Nn, 256>>>(x, gamma, beta);

    // qkv = xn @ w_qkv   [16384,512]@[512,1536]
    tgemm<<<dim3(1536 / 64, 16384 / 128, 1), 256>>>(
        p_xn, w_qkv, p_qkv, 512, 512, 1536, 1536, 0, 0, 0, 0, 1.f, 0.f,
        nullptr, nullptr, nullptr);
    k_split<<<(Bb * Nn * 3 * DIMV) / 256, 256>>>();
    k_land<<<(2 * BHc * Mm * Dd) / 256, 256>>>();

    // S1 = q @ kl^T   per-bh [4096,64]@[64,256]^T
    tgemm<<<dim3(4, 32, 32), 256>>>(p_q, p_kl, p_s1, 64, 64, 64, 256,
        (long)Nn * Dd, (long)Mm * Dd, (long)Nn * Mm, 1, 1.f, 0.f, nullptr, nullptr, nullptr);
    k_softmax<1><<<BHc * Nn, 256>>>(p_s1);

    // A2 = ql @ kl^T   [256,64]@[64,256]^T
    tgemm<<<dim3(4, 2, 32), 256>>>(p_ql, p_kl, p_a2, 64, 64, 64, 256,
        (long)Mm * Dd, (long)Mm * Dd, (long)Mm * Mm, 1, 1.f, 0.f, nullptr, nullptr, nullptr);
    k_softmax<1><<<BHc * Mm, 256>>>(p_a2);

    // S3 = ql @ k^T   [256,64]@[64,4096]^T
    tgemm<<<dim3(64, 2, 32), 256>>>(p_ql, p_k, p_s3, 64, 64, 64, 4096,
        (long)Mm * Dd, (long)Nn * Dd, (long)Mm * Nn, 1, 1.f, 0.f, nullptr, nullptr, nullptr);
    k_softmax<16><<<BHc * Mm, 256>>>(p_s3);

    // pinv init
    k_sums<<<BHc, 256>>>(p_a2);
    k_z0<<<(BHc * Mm * Mm) / 256, 256>>>(p_a2);

    // Newton-Schulz: 6 iters, each 4 batched 256^3 GEMMs
    float* zc = p_z; float* zo = p_zn;
    long sq = (long)Mm * Mm;
    for (int it = 0; it < 6; it++) {
        tgemm<<<dim3(4, 2, 32), 256>>>(p_a2, zc, p_az, 256, 256, 256, 256,
            sq, sq, sq, 0, 1.f, 0.f, nullptr, nullptr, nullptr);
        tgemm<<<dim3(4, 2, 32), 256>>>(p_az, p_az, p_w1, 256, 256, 256, 256,
            sq, sq, sq, 0, -1.f, 7.f, p_az, nullptr, nullptr);
        tgemm<<<dim3(4, 2, 32), 256>>>(p_az, p_w1, p_w2, 256, 256, 256, 256,
            sq, sq, sq, 0, -1.f, 15.f, p_az, nullptr, nullptr);
        tgemm<<<dim3(4, 2, 32), 256>>>(zc, p_w2, zo, 256, 256, 256, 256,
            sq, sq, sq, 0, -0.25f, 3.25f, zc, nullptr, nullptr);
        float* t = zc; zc = zo; zo = t;
    }

    // A3V = S3 @ v   [256,4096]@[4096,64]
    tgemm<<<dim3(1, 2, 32), 256>>>(p_s3, p_v, p_a3v, 4096, 4096, 64, 64,
        (long)Mm * Nn, (long)Nn * Dd, (long)Mm * Dd, 0, 1.f, 0.f, nullptr, nullptr, nullptr);

    // T1 = S1 @ Z   [4096,256]@[256,256]
    tgemm<<<dim3(4, 32, 32), 256>>>(p_s1, zc, p_t1, 256, 256, 256, 256,
        (long)Nn * Mm, sq, (long)Nn * Mm, 0, 1.f, 0.f, nullptr, nullptr, nullptr);

    // OUTH = T1 @ A3V   [4096,256]@[256,64]
    tgemm<<<dim3(1, 32, 32), 256>>>(p_t1, p_a3v, p_oh, 256, 256, 64, 64,
        (long)Nn * Mm, (long)Mm * Dd, (long)Nn * Dd, 0, 1.f, 0.f, nullptr, nullptr, nullptr);

    // residual depthwise conv of v added to OUTH
    k_conv<<<(BHc * Nn * Dd) / 256, 256>>>(conv_w);
    k_merge<<<(Bb * Nn * DIMV) / 256, 256>>>();

    // final: out = OUTM @ w_out + b_out + x
    tgemm<<<dim3(512 / 64, 16384 / 128, 1), 256>>>(p_om, w_out, out, 512, 512, 512, 512,
        0, 0, 0, 0, 1.f, 0.f, nullptr, b_out, x);
}

// round 3
// speedup vs baseline: 2.2803x; 1.5104x over previous
#include <cuda_runtime.h>
#include <cstddef>

#define Bb 4
#define Nn 4096
#define DIMV 512
#define Hh 8
#define Dd 64
#define Mm 256
#define BHc 32
#define QSCALE 0.125f

// ---------------- scratch ----------------
__device__ float g_q   [BHc*Nn*Dd];
__device__ float g_k   [BHc*Nn*Dd];
__device__ float g_v   [BHc*Nn*Dd];
__device__ float g_ql  [BHc*Mm*Dd];
__device__ float g_kl  [BHc*Mm*Dd];
__device__ float g_a2  [BHc*Mm*Mm];
__device__ float g_z   [BHc*Mm*Mm];
__device__ float g_zn  [BHc*Mm*Mm];
__device__ float g_az  [BHc*Mm*Mm];
__device__ float g_w1  [BHc*Mm*Mm];
__device__ float g_w2  [BHc*Mm*Mm];
__device__ float g_a3v [BHc*Mm*Dd];
__device__ float g_wm  [BHc*Mm*Dd];
__device__ float g_outh[BHc*Nn*Dd];
__device__ float g_mu  [Bb*Nn];
__device__ float g_rs  [Bb*Nn];
__device__ float g_ms1, g_ms2;

__device__ __forceinline__ unsigned f2tf(float f) {
    unsigned u;
    asm("cvt.rna.tf32.f32 %0, %1;" : "=r"(u) : "f"(f));
    return u;
}

__device__ __forceinline__ void mma8(float* c, const unsigned* a, const unsigned* b) {
    asm volatile("mma.sync.aligned.m16n8k8.row.col.f32.tf32.tf32.f32 "
                 "{%0,%1,%2,%3},{%4,%5,%6,%7},{%8,%9},{%0,%1,%2,%3};"
                 : "+f"(c[0]), "+f"(c[1]), "+f"(c[2]), "+f"(c[3])
                 : "r"(a[0]), "r"(a[1]), "r"(a[2]), "r"(a[3]), "r"(b[0]), "r"(b[1]));
}

// ---------------- small kernels ----------------
__global__ void k_init() { g_ms1 = 0.f; g_ms2 = 0.f; }

__global__ void k_lnstats(const float* __restrict__ x) {
    int r = blockIdx.x, t = threadIdx.x;
    const float* xp = x + (size_t)r * DIMV;
    float v0 = xp[t], v1 = xp[t + 256];
    __shared__ float red[256];
    red[t] = v0 + v1; __syncthreads();
    for (int s = 128; s; s >>= 1) { if (t < s) red[t] += red[t + s]; __syncthreads(); }
    float mean = red[0] * (1.f / 512.f);
    __syncthreads();
    float d0 = v0 - mean, d1 = v1 - mean;
    red[t] = d0 * d0 + d1 * d1; __syncthreads();
    for (int s = 128; s; s >>= 1) { if (t < s) red[t] += red[t + s]; __syncthreads(); }
    if (t == 0) { g_mu[r] = mean; g_rs[r] = rsqrtf(red[0] * (1.f / 512.f) + 1e-5f); }
}

__global__ void k_land() {
    int idx = blockIdx.x * 256 + threadIdx.x;
    int sel = idx >= (BHc * Mm * Dd);
    int e = idx & (BHc * Mm * Dd - 1);
    int bh = e >> 14, j = (e >> 6) & 255, d = e & 63;
    const float* src = sel ? g_k : g_q;
    const float* p = src + ((size_t)bh * 4096 + j * 16) * 64 + d;
    float s = 0.f;
#pragma unroll
    for (int t = 0; t < 16; t++) s += p[t * 64];
    (sel ? g_kl : g_ql)[(size_t)bh * 16384 + j * 64 + d] = s * (1.f / 16.f);
}

template <int E>
__global__ void k_softmax(float* __restrict__ p) {
    int row = blockIdx.x, t = threadIdx.x;
    p += (size_t)row * (256 * E);
    float rv[E];
    float m = -1e30f;
#pragma unroll
    for (int i = 0; i < E; i++) { rv[i] = p[t + (i << 8)]; m = fmaxf(m, rv[i]); }
    __shared__ float red[256];
    red[t] = m; __syncthreads();
    for (int s = 128; s; s >>= 1) { if (t < s) red[t] = fmaxf(red[t], red[t + s]); __syncthreads(); }
    m = red[0]; __syncthreads();
    float sum = 0.f;
#pragma unroll
    for (int i = 0; i < E; i++) { rv[i] = __expf(rv[i] - m); sum += rv[i]; }
    red[t] = sum; __syncthreads();
    for (int s = 128; s; s >>= 1) { if (t < s) red[t] += red[t + s]; __syncthreads(); }
    float inv = 1.f / red[0];
#pragma unroll
    for (int i = 0; i < E; i++) p[t + (i << 8)] = rv[i] * inv;
}

__global__ void k_sums(const float* __restrict__ a) {
    int mat = blockIdx.x, t = threadIdx.x;
    const float* A = a + (size_t)mat * 65536;
    float cs = 0.f, rs = 0.f;
    for (int i = 0; i < 256; i++) { cs += A[i * 256 + t]; rs += A[t * 256 + i]; }
    __shared__ float red[256];
    red[t] = rs; __syncthreads();
    for (int s = 128; s; s >>= 1) { if (t < s) red[t] = fmaxf(red[t], red[t + s]); __syncthreads(); }
    if (!t) atomicMax((int*)&g_ms1, __float_as_int(red[0]));
    __syncthreads();
    red[t] = cs; __syncthreads();
    for (int s = 128; s; s >>= 1) { if (t < s) red[t] = fmaxf(red[t], red[t + s]); __syncthreads(); }
    if (!t) atomicMax((int*)&g_ms2, __float_as_int(red[0]));
}

__global__ void k_z0(const float* __restrict__ a) {
    int idx = blockIdx.x * 256 + threadIdx.x;
    float inv = 1.f / (g_ms1 * g_ms2);
    int mat = idx >> 16, r = (idx >> 8) & 255, c = idx & 255;
    g_z[idx] = a[((size_t)mat << 16) + (c << 8) + r] * inv;
}

__global__ void k_conv2(const float* __restrict__ w) {
    int nt = blockIdx.x, bh = blockIdx.y;
    __shared__ float vs[160][64];
    const float* vp = g_v + ((size_t)bh << 18);
    int n0 = nt * 128;
    for (int i = threadIdx.x; i < 160 * 16; i += 256) {
        int r = i >> 4, cg = (i & 15) * 4;
        int n = n0 - 16 + r;
        float4 val = (n >= 0 && n < 4096) ? *(const float4*)(vp + (size_t)n * 64 + cg)
                                          : make_float4(0.f, 0.f, 0.f, 0.f);
        *(float4*)&vs[r][cg] = val;
    }
    __syncthreads();
    int h = bh & 7;
    float wr[33];
#pragma unroll
    for (int t = 0; t < 33; t++) wr[t] = w[h * 33 + t];
    int d = threadIdx.x & 63, nl = threadIdx.x >> 6;
    for (int p = 0; p < 32; p++) {
        int n = nl + p * 4;
        float acc = 0.f;
#pragma unroll
        for (int t = 0; t < 33; t++) acc += wr[t] * vs[n + t][d];
        g_outh[((size_t)bh * 4096 + n0 + n) * 64 + d] += acc;
    }
}

// ---------------- generic TF32 batched GEMM ----------------
// mode 0: normal epilogue/A-load
// mode 2: A remapped from g_outh (head-merge on the fly)
// mode 3: A = LayerNorm(x) on the fly (gammaP/betaP) AND qkv split epilogue
__global__ __launch_bounds__(256) void tgemm(
    const float* __restrict__ A, const float* __restrict__ Bm,
    float* __restrict__ C, int Kr,
    int lda, int ldb, int ldc,
    long sA, long sB, long sC,
    int transB, float cM, float cA, const float* __restrict__ AE,
    const float* __restrict__ bias, const float* __restrict__ resid,
    int mode, const float* __restrict__ gammaP, const float* __restrict__ betaP) {
    int bz = blockIdx.z;
    A  += (size_t)bz * sA;
    Bm += (size_t)bz * sB;
    C  += (size_t)bz * sC;

    __shared__ unsigned As[128][20];
    __shared__ unsigned Bs[64][20];

    int tid = threadIdx.x, lane = tid & 31, w = tid >> 5;
    int wr = w >> 1, wc = w & 1;
    int rowBase = blockIdx.y * 128, colBase = blockIdx.x * 64;

    float acc[2][4][4];
#pragma unroll
    for (int mi = 0; mi < 2; mi++)
#pragma unroll
        for (int ni = 0; ni < 4; ni++)
#pragma unroll
            for (int q = 0; q < 4; q++) acc[mi][ni][q] = 0.f;

    for (int k0 = 0; k0 < Kr; k0 += 16) {
#pragma unroll
        for (int i = 0; i < 2; i++) {
            int idx = tid + i * 256;
            int r = idx >> 2, cg = (idx & 3) * 4;
            float4 a4;
            if (mode == 2) {
                int gr = rowBase + r;
                int b = gr >> 12, n = gr & 4095;
                int kk = k0 + cg, h = kk >> 6, d = kk & 63;
                a4 = *(const float4*)(g_outh + (((size_t)(b * 8 + h)) * 4096 + n) * 64 + d);
            } else {
                a4 = *(const float4*)(A + (size_t)(rowBase + r) * lda + k0 + cg);
            }
            if (mode == 3) {
                float mu = g_mu[rowBase + r], rsd = g_rs[rowBase + r];
                float4 g4 = *(const float4*)(gammaP + k0 + cg);
                float4 b4 = *(const float4*)(betaP + k0 + cg);
                a4.x = (a4.x - mu) * rsd * g4.x + b4.x;
                a4.y = (a4.y - mu) * rsd * g4.y + b4.y;
                a4.z = (a4.z - mu) * rsd * g4.z + b4.z;
                a4.w = (a4.w - mu) * rsd * g4.w + b4.w;
            }
            uint4 u;
            u.x = f2tf(a4.x); u.y = f2tf(a4.y); u.z = f2tf(a4.z); u.w = f2tf(a4.w);
            *(uint4*)&As[r][cg] = u;
        }
        if (transB) {
            int r = tid >> 2, cg = (tid & 3) * 4;
            float4 b4 = *(const float4*)(Bm + (size_t)(colBase + r) * ldb + k0 + cg);
            uint4 u;
            u.x = f2tf(b4.x); u.y = f2tf(b4.y); u.z = f2tf(b4.z); u.w = f2tf(b4.w);
            *(uint4*)&Bs[r][cg] = u;
        } else {
            int kk = tid >> 4, n0 = (tid & 15) * 4;
            float4 b4 = *(const float4*)(Bm + (size_t)(k0 + kk) * ldb + colBase + n0);
            Bs[n0 + 0][kk] = f2tf(b4.x);
            Bs[n0 + 1][kk] = f2tf(b4.y);
            Bs[n0 + 2][kk] = f2tf(b4.z);
            Bs[n0 + 3][kk] = f2tf(b4.w);
        }
        __syncthreads();

#pragma unroll
        for (int ks = 0; ks < 2; ks++) {
            int kb = ks * 8;
            unsigned ar[2][4], br[4][2];
#pragma unroll
            for (int mi = 0; mi < 2; mi++) {
                int r = wr * 32 + mi * 16 + (lane >> 2);
                ar[mi][0] = As[r][kb + (lane & 3)];
                ar[mi][1] = As[r + 8][kb + (lane & 3)];
                ar[mi][2] = As[r][kb + (lane & 3) + 4];
                ar[mi][3] = As[r + 8][kb + (lane & 3) + 4];
            }
#pragma unroll
            for (int ni = 0; ni < 4; ni++) {
                int n = wc * 32 + ni * 8 + (lane >> 2);
                br[ni][0] = Bs[n][kb + (lane & 3)];
                br[ni][1] = Bs[n][kb + (lane & 3) + 4];
            }
#pragma unroll
            for (int mi = 0; mi < 2; mi++)
#pragma unroll
                for (int ni = 0; ni < 4; ni++) mma8(acc[mi][ni], ar[mi], br[ni]);
        }
        __syncthreads();
    }

#pragma unroll
    for (int mi = 0; mi < 2; mi++) {
#pragma unroll
        for (int ni = 0; ni < 4; ni++) {
            int r0 = rowBase + wr * 32 + mi * 16 + (lane >> 2);
            int c0 = colBase + wc * 32 + ni * 8 + (lane & 3) * 2;
#pragma unroll
            for (int q = 0; q < 4; q++) {
                int r = r0 + (q >> 1) * 8;
                int c = c0 + (q & 1);
                float v = cM * acc[mi][ni][q];
                if (mode == 3) {
                    int which = c >> 9, inner = c & 511;
                    int h = inner >> 6, d = inner & 63;
                    int b = r >> 12, n = r & 4095;
                    size_t dst = (((size_t)(b * 8 + h)) * 4096 + n) * 64 + d;
                    if (which == 0)      g_q[dst] = v * QSCALE;
                    else if (which == 1) g_k[dst] = v;
                    else                 g_v[dst] = v;
                } else {
                    if (AE)    v += cA * AE[(size_t)bz * sA + (size_t)r * lda + c];
                    if (bias)  v += bias[c];
                    if (resid) v += resid[(size_t)r * ldc + c];
                    C[(size_t)r * ldc + c] = v;
                }
            }
        }
    }
}

// ---------------- flash-style attn3 @ v ----------------
__global__ __launch_bounds__(128) void k_flash() {
    int rt = blockIdx.x, bh = blockIdx.y;
    extern __shared__ unsigned sm[];
    unsigned* Qs = sm;
    unsigned* Ks = Qs + 64 * 68;
    unsigned* Vs = Ks + 64 * 68;
    unsigned* Ps = Vs + 64 * 72;
    const float* qlp = g_ql + (size_t)bh * 16384 + (size_t)rt * 64 * 64;
    const float* kp  = g_k + ((size_t)bh << 18);
    const float* vp  = g_v + ((size_t)bh << 18);
    int tid = threadIdx.x, lane = tid & 31, w = tid >> 5;
    int r0 = lane >> 2, kq = lane & 3;
    int wrow = w * 16;

    for (int i = tid; i < 64 * 16; i += 128) {
        int r = i >> 4, cg = (i & 15) * 4;
        float4 a4 = *(const float4*)(qlp + r * 64 + cg);
        Qs[r * 68 + cg + 0] = f2tf(a4.x); Qs[r * 68 + cg + 1] = f2tf(a4.y);
        Qs[r * 68 + cg + 2] = f2tf(a4.z); Qs[r * 68 + cg + 3] = f2tf(a4.w);
    }

    float O[8][4];
#pragma unroll
    for (int j = 0; j < 8; j++)
#pragma unroll
        for (int q = 0; q < 4; q++) O[j][q] = 0.f;
    float m0 = -1e30f, m1 = -1e30f, l0 = 0.f, l1 = 0.f;

    for (int n0 = 0; n0 < 4096; n0 += 64) {
        __syncthreads();
        for (int i = tid; i < 64 * 16; i += 128) {
            int r = i >> 4, cg = (i & 15) * 4;
            float4 k4 = *(const float4*)(kp + (size_t)(n0 + r) * 64 + cg);
            float4 v4 = *(const float4*)(vp + (size_t)(n0 + r) * 64 + cg);
            Ks[r * 68 + cg + 0] = f2tf(k4.x); Ks[r * 68 + cg + 1] = f2tf(k4.y);
            Ks[r * 68 + cg + 2] = f2tf(k4.z); Ks[r * 68 + cg + 3] = f2tf(k4.w);
            Vs[r * 72 + cg + 0] = f2tf(v4.x); Vs[r * 72 + cg + 1] = f2tf(v4.y);
            Vs[r * 72 + cg + 2] = f2tf(v4.z); Vs[r * 72 + cg + 3] = f2tf(v4.w);
        }
        __syncthreads();

        float sc[8][4];
#pragma unroll
        for (int j = 0; j < 8; j++)
#pragma unroll
            for (int q = 0; q < 4; q++) sc[j][q] = 0.f;
#pragma unroll
        for (int ks = 0; ks < 8; ks++) {
            int kb = ks * 8;
            unsigned a[4];
            a[0] = Qs[(wrow + r0) * 68 + kb + kq];
            a[1] = Qs[(wrow + r0 + 8) * 68 + kb + kq];
            a[2] = Qs[(wrow + r0) * 68 + kb + kq + 4];
            a[3] = Qs[(wrow + r0 + 8) * 68 + kb + kq + 4];
#pragma unroll
            for (int j = 0; j < 8; j++) {
                unsigned b[2] = { Ks[(j * 8 + r0) * 68 + kb + kq],
                                  Ks[(j * 8 + r0) * 68 + kb + kq + 4] };
                mma8(sc[j], a, b);
            }
        }
        float tm0 = -1e30f, tm1 = -1e30f;
#pragma unroll
        for (int j = 0; j < 8; j++) {
            tm0 = fmaxf(tm0, fmaxf(sc[j][0], sc[j][1]));
            tm1 = fmaxf(tm1, fmaxf(sc[j][2], sc[j][3]));
        }
        tm0 = fmaxf(tm0, __shfl_xor_sync(0xffffffffu, tm0, 1));
        tm0 = fmaxf(tm0, __shfl_xor_sync(0xffffffffu, tm0, 2));
        tm1 = fmaxf(tm1, __shfl_xor_sync(0xffffffffu, tm1, 1));
        tm1 = fmaxf(tm1, __shfl_xor_sync(0xffffffffu, tm1, 2));
        float mn0 = fmaxf(m0, tm0), mn1 = fmaxf(m1, tm1);
        float al0 = __expf(m0 - mn0), al1 = __expf(m1 - mn1);
        float ts0 = 0.f, ts1 = 0.f;
#pragma unroll
        for (int j = 0; j < 8; j++) {
            sc[j][0] = __expf(sc[j][0] - mn0); sc[j][1] = __expf(sc[j][1] - mn0);
            sc[j][2] = __expf(sc[j][2] - mn1); sc[j][3] = __expf(sc[j][3] - mn1);
            ts0 += sc[j][0] + sc[j][1];
            ts1 += sc[j][2] + sc[j][3];
        }
        ts0 += __shfl_xor_sync(0xffffffffu, ts0, 1); ts0 += __shfl_xor_sync(0xffffffffu, ts0, 2);
        ts1 += __shfl_xor_sync(0xffffffffu, ts1, 1); ts1 += __shfl_xor_sync(0xffffffffu, ts1, 2);
        l0 = l0 * al0 + ts0; l1 = l1 * al1 + ts1;
        m0 = mn0; m1 = mn1;
#pragma unroll
        for (int j = 0; j < 8; j++) {
            O[j][0] *= al0; O[j][1] *= al0; O[j][2] *= al1; O[j][3] *= al1;
        }
#pragma unroll
        for (int j = 0; j < 8; j++) {
            int c = j * 8 + kq * 2;
            Ps[(wrow + r0) * 68 + c]         = f2tf(sc[j][0]);
            Ps[(wrow + r0) * 68 + c + 1]     = f2tf(sc[j][1]);
            Ps[(wrow + r0 + 8) * 68 + c]     = f2tf(sc[j][2]);
            Ps[(wrow + r0 + 8) * 68 + c + 1] = f2tf(sc[j][3]);
        }
        __syncwarp();
#pragma unroll
        for (int ks = 0; ks < 8; ks++) {
            int kb = ks * 8;
            unsigned a[4];
            a[0] = Ps[(wrow + r0) * 68 + kb + kq];
            a[1] = Ps[(wrow + r0 + 8) * 68 + kb + kq];
            a[2] = Ps[(wrow + r0) * 68 + kb + kq + 4];
            a[3] = Ps[(wrow + r0 + 8) * 68 + kb + kq + 4];
#pragma unroll
            for (int j = 0; j < 8; j++) {
                unsigned b[2] = { Vs[(kb + kq) * 72 + j * 8 + r0],
                                  Vs[(kb + kq + 4) * 72 + j * 8 + r0] };
                mma8(O[j], a, b);
            }
        }
    }
    float il0 = 1.f / l0, il1 = 1.f / l1;
    float* op = g_a3v + (size_t)bh * 16384 + (size_t)rt * 64 * 64;
#pragma unroll
    for (int j = 0; j < 8; j++) {
        int c = j * 8 + kq * 2;
        op[(wrow + r0) * 64 + c]         = O[j][0] * il0;
        op[(wrow + r0) * 64 + c + 1]     = O[j][1] * il0;
        op[(wrow + r0 + 8) * 64 + c]     = O[j][2] * il1;
        op[(wrow + r0 + 8) * 64 + c + 1] = O[j][3] * il1;
    }
}

// ---------------- fused attn1: outh = softmax(q @ kl^T) @ W ----------------
__global__ __launch_bounds__(256, 1) void k_attn1() {
    int bx = blockIdx.x, bh = blockIdx.y;
    extern __shared__ unsigned sm[];
    unsigned* KLs = sm;
    unsigned* Qs  = sm + 256 * 68;
    unsigned* Ps  = sm + 256 * 68 + 128 * 68;
    unsigned* Ws  = sm;
    const float* qp  = g_q + ((size_t)bh << 18) + (size_t)bx * 128 * 64;
    const float* klp = g_kl + (size_t)bh * 16384;
    const float* wp  = g_wm + (size_t)bh * 16384;
    int tid = threadIdx.x, lane = tid & 31, w = tid >> 5;
    int r0 = lane >> 2, kq = lane & 3;
    int wrow = w * 16;

    for (int i = tid; i < 128 * 16; i += 256) {
        int r = i >> 4, cg = (i & 15) * 4;
        float4 a4 = *(const float4*)(qp + r * 64 + cg);
        Qs[r * 68 + cg + 0] = f2tf(a4.x); Qs[r * 68 + cg + 1] = f2tf(a4.y);
        Qs[r * 68 + cg + 2] = f2tf(a4.z); Qs[r * 68 + cg + 3] = f2tf(a4.w);
    }
    for (int i = tid; i < 256 * 16; i += 256) {
        int r = i >> 4, cg = (i & 15) * 4;
        float4 b4 = *(const float4*)(klp + r * 64 + cg);
        KLs[r * 68 + cg + 0] = f2tf(b4.x); KLs[r * 68 + cg + 1] = f2tf(b4.y);
        KLs[r * 68 + cg + 2] = f2tf(b4.z); KLs[r * 68 + cg + 3] = f2tf(b4.w);
    }
    __syncthreads();

    float sc[32][4];
#pragma unroll
    for (int j = 0; j < 32; j++)
#pragma unroll
        for (int q = 0; q < 4; q++) sc[j][q] = 0.f;
#pragma unroll
    for (int ks = 0; ks < 8; ks++) {
        int kb = ks * 8;
        unsigned a[4];
        a[0] = Qs[(wrow + r0) * 68 + kb + kq];
        a[1] = Qs[(wrow + r0 + 8) * 68 + kb + kq];
        a[2] = Qs[(wrow + r0) * 68 + kb + kq + 4];
        a[3] = Qs[(wrow + r0 + 8) * 68 + kb + kq + 4];
#pragma unroll
        for (int j = 0; j < 32; j++) {
            unsigned b[2] = { KLs[(j * 8 + r0) * 68 + kb + kq],
                              KLs[(j * 8 + r0) * 68 + kb + kq + 4] };
            mma8(sc[j], a, b);
        }
    }
    float m0 = -1e30f, m1 = -1e30f;
#pragma unroll
    for (int j = 0; j < 32; j++) {
        m0 = fmaxf(m0, fmaxf(sc[j][0], sc[j][1]));
        m1 = fmaxf(m1, fmaxf(sc[j][2], sc[j][3]));
    }
    m0 = fmaxf(m0, __shfl_xor_sync(0xffffffffu, m0, 1));
    m0 = fmaxf(m0, __shfl_xor_sync(0xffffffffu, m0, 2));
    m1 = fmaxf(m1, __shfl_xor_sync(0xffffffffu, m1, 1));
    m1 = fmaxf(m1, __shfl_xor_sync(0xffffffffu, m1, 2));
    float l0 = 0.f, l1 = 0.f;
#pragma unroll
    for (int j = 0; j < 32; j++) {
        sc[j][0] = __expf(sc[j][0] - m0); sc[j][1] = __expf(sc[j][1] - m0);
        sc[j][2] = __expf(sc[j][2] - m1); sc[j][3] = __expf(sc[j][3] - m1);
        l0 += sc[j][0] + sc[j][1];
        l1 += sc[j][2] + sc[j][3];
    }
    l0 += __shfl_xor_sync(0xffffffffu, l0, 1); l0 += __shfl_xor_sync(0xffffffffu, l0, 2);
    l1 += __shfl_xor_sync(0xffffffffu, l1, 1); l1 += __shfl_xor_sync(0xffffffffu, l1, 2);

    __syncthreads();
    for (int i = tid; i < 256 * 16; i += 256) {
        int r = i >> 4, cg = (i & 15) * 4;
        float4 b4 = *(const float4*)(wp + r * 64 + cg);
        Ws[r * 72 + cg + 0] = f2tf(b4.x); Ws[r * 72 + cg + 1] = f2tf(b4.y);
        Ws[r * 72 + cg + 2] = f2tf(b4.z); Ws[r * 72 + cg + 3] = f2tf(b4.w);
    }
    __syncthreads();

    float O[8][4];
#pragma unroll
    for (int j = 0; j < 8; j++)
#pragma unroll
        for (int q = 0; q < 4; q++) O[j][q] = 0.f;

#pragma unroll
    for (int ch = 0; ch < 4; ch++) {
#pragma unroll
        for (int jj = 0; jj < 8; jj++) {
            int j = ch * 8 + jj;
            int c = jj * 8 + kq * 2;
            Ps[(wrow + r0) * 68 + c]         = f2tf(sc[j][0]);
            Ps[(wrow + r0) * 68 + c + 1]     = f2tf(sc[j][1]);
            Ps[(wrow + r0 + 8) * 68 + c]     = f2tf(sc[j][2]);
            Ps[(wrow + r0 + 8) * 68 + c + 1] = f2tf(sc[j][3]);
        }
        __syncwarp();
#pragma unroll
        for (int ks = 0; ks < 8; ks++) {
            int kb = ks * 8;
            unsigned a[4];
            a[0] = Ps[(wrow + r0) * 68 + kb + kq];
            a[1] = Ps[(wrow + r0 + 8) * 68 + kb + kq];
            a[2] = Ps[(wrow + r0) * 68 + kb + kq + 4];
            a[3] = Ps[(wrow + r0 + 8) * 68 + kb + kq + 4];
#pragma unroll
            for (int j = 0; j < 8; j++) {
                unsigned b[2] = { Ws[(ch * 64 + kb + kq) * 72 + j * 8 + r0],
                                  Ws[(ch * 64 + kb + kq + 4) * 72 + j * 8 + r0] };
                mma8(O[j], a, b);
            }
        }
        __syncwarp();
    }

    float il0 = 1.f / l0, il1 = 1.f / l1;
    float* op = g_outh + ((size_t)bh << 18) + (size_t)bx * 128 * 64;
#pragma unroll
    for (int j = 0; j < 8; j++) {
        int c = j * 8 + kq * 2;
        op[(wrow + r0) * 64 + c]         = O[j][0] * il0;
        op[(wrow + r0) * 64 + c + 1]     = O[j][1] * il0;
        op[(wrow + r0 + 8) * 64 + c]     = O[j][2] * il1;
        op[(wrow + r0 + 8) * 64 + c + 1] = O[j][3] * il1;
    }
}

// ---------------- host orchestration ----------------
extern "C" void kernel_launch(void* const* d_in, const int* in_sizes, int n_in,
                              void* d_out, int out_size) {
    const float* x      = (const float*)d_in[0];
    const float* gamma  = (const float*)d_in[1];
    const float* beta   = (const float*)d_in[2];
    const float* w_qkv  = (const float*)d_in[3];
    const float* w_out  = (const float*)d_in[4];
    const float* b_out  = (const float*)d_in[5];
    const float* conv_w = (const float*)d_in[6];
    float* out = (float*)d_out;

    void* tp;
    cudaGetSymbolAddress(&tp, g_q);    float* p_q   = (float*)tp;
    cudaGetSymbolAddress(&tp, g_ql);   float* p_ql  = (float*)tp;
    cudaGetSymbolAddress(&tp, g_kl);   float* p_kl  = (float*)tp;
    cudaGetSymbolAddress(&tp, g_a2);   float* p_a2  = (float*)tp;
    cudaGetSymbolAddress(&tp, g_z);    float* p_z   = (float*)tp;
    cudaGetSymbolAddress(&tp, g_zn);   float* p_zn  = (float*)tp;
    cudaGetSymbolAddress(&tp, g_az);   float* p_az  = (float*)tp;
    cudaGetSymbolAddress(&tp, g_w1);   float* p_w1  = (float*)tp;
    cudaGetSymbolAddress(&tp, g_w2);   float* p_w2  = (float*)tp;
    cudaGetSymbolAddress(&tp, g_a3v);  float* p_a3v = (float*)tp;
    cudaGetSymbolAddress(&tp, g_wm);   float* p_wm  = (float*)tp;

    cudaFuncSetAttribute(k_flash, cudaFuncAttributeMaxDynamicSharedMemorySize, 70656);
    cudaFuncSetAttribute(k_attn1, cudaFuncAttributeMaxDynamicSharedMemorySize, 139264);

    k_init<<<1, 1>>>();
    k_lnstats<<<Bb * Nn, 256>>>(x);

    // qkv = LN(x) @ w_qkv, scattered directly into q/k/v (mode 3)
    tgemm<<<dim3(24, 128, 1), 256>>>(x, w_qkv, p_q, 512, 512, 1536, 1536,
        0, 0, 0, 0, 1.f, 0.f, nullptr, nullptr, nullptr, 3, gamma, beta);

    k_land<<<(2 * BHc * Mm * Dd) / 256, 256>>>();

    // A2 = ql @ kl^T + softmax
    tgemm<<<dim3(4, 2, 32), 256>>>(p_ql, p_kl, p_a2, 64, 64, 64, 256,
        (long)Mm * Dd, (long)Mm * Dd, (long)Mm * Mm, 1, 1.f, 0.f, nullptr, nullptr, nullptr,
        0, nullptr, nullptr);
    k_softmax<1><<<BHc * Mm, 256>>>(p_a2);

    k_sums<<<BHc, 256>>>(p_a2);
    k_z0<<<(BHc * Mm * Mm) / 256, 256>>>(p_a2);

    // flash attn3 @ v (independent of pinv chain)
    k_flash<<<dim3(4, 32), 128, 70656>>>();

    // Newton-Schulz
    float* zc = p_z; float* zo = p_zn;
    long sq = (long)Mm * Mm;
    for (int it = 0; it < 6; it++) {
        tgemm<<<dim3(4, 2, 32), 256>>>(p_a2, zc, p_az, 256, 256, 256, 256,
            sq, sq, sq, 0, 1.f, 0.f, nullptr, nullptr, nullptr, 0, nullptr, nullptr);
        tgemm<<<dim3(4, 2, 32), 256>>>(p_az, p_az, p_w1, 256, 256, 256, 256,
            sq, sq, sq, 0, -1.f, 7.f, p_az, nullptr, nullptr, 0, nullptr, nullptr);
        tgemm<<<dim3(4, 2, 32), 256>>>(p_az, p_w1, p_w2, 256, 256, 256, 256,
            sq, sq, sq, 0, -1.f, 15.f, p_az, nullptr, nullptr, 0, nullptr, nullptr);
        tgemm<<<dim3(4, 2, 32), 256>>>(zc, p_w2, zo, 256, 256, 256, 256,
            sq, sq, sq, 0, -0.25f, 3.25f, zc, nullptr, nullptr, 0, nullptr, nullptr);
        float* t = zc; zc = zo; zo = t;
    }

    // W = Z @ a3v   [256,256]@[256,64]
    tgemm<<<dim3(1, 2, 32), 256>>>(zc, p_a3v, p_wm, 256, 256, 64, 64,
        sq, (long)Mm * Dd, (long)Mm * Dd, 0, 1.f, 0.f, nullptr, nullptr, nullptr,
        0, nullptr, nullptr);

    // fused attn1 -> outh
    k_attn1<<<dim3(32, 32), 256, 139264>>>();

    // conv residual add
    k_conv2<<<dim3(32, 32), 256>>>(conv_w);

    // final: out = merge(outh) @ w_out + b_out + x   (mode 2 A-remap)
    tgemm<<<dim3(8, 128, 1), 256>>>(nullptr, w_out, out, 512, 512, 512, 512,
        0, 0, 0, 0, 1.f, 0.f, nullptr, b_out, x, 2, nullptr, nullptr);
}